// round 1
// baseline (speedup 1.0000x reference)
#include <cuda_runtime.h>
#include <cstddef>

// ---------------------------------------------------------------------------
// BaseMultiHeadAttention: fused projections + flash attention w/ diagonal term
// Shapes: b=4, n=2048, d=512, H=8, DH=64  (fp32 throughout)
//
//   Q = xq@Wq, K = xk@Wk, V = xv@Wv, XQK = xq@Wk, XQV = xq@Wv
//   per (b,h): S = (Q*scale) @ K^T, plus diagonal logit dot(Q*scale, XQK)
//   softmax over [n keys + diag], O = P@V + p_diag * XQV
//   out = O @ Wo + bo
// ---------------------------------------------------------------------------

#define SSTR 68  // smem row stride (floats): 64 + 4 pad, multiple of 4 for float4

// Scratch (device globals: allocation-free per harness rules). 16 MB each.
__device__ float g_Q  [8192 * 512];
__device__ float g_K  [8192 * 512];
__device__ float g_V  [8192 * 512];
__device__ float g_XQK[8192 * 512];
__device__ float g_XQV[8192 * 512];
__device__ float g_AO [8192 * 512];

// ---------------------------------------------------------------------------
// GEMM: C[M,N] = A[M,K] @ B[K,N] (+ bias), 128x128 tile, BK=8, 256 threads,
// 8x8 register micro-tile (split 4+4 pattern).
// ---------------------------------------------------------------------------
__global__ __launch_bounds__(256, 2)
void gemm_tiled(const float* __restrict__ A, const float* __restrict__ B,
                const float* __restrict__ bias, float* __restrict__ C,
                int M, int N, int K)
{
    __shared__ float As[8][128];  // [k][m]
    __shared__ float Bs[8][128];  // [k][n]

    const int tid = threadIdx.x;
    const int tx = tid & 15;
    const int ty = tid >> 4;
    const int rowBase = blockIdx.y * 128;
    const int colBase = blockIdx.x * 128;
    const int aRow = tid >> 1;          // 0..127
    const int aCol = (tid & 1) << 2;    // 0 or 4
    const int bRow = tid >> 5;          // 0..7
    const int bCol = (tid & 31) << 2;   // 0..124

    float acc[8][8];
    #pragma unroll
    for (int i = 0; i < 8; i++)
        #pragma unroll
        for (int j = 0; j < 8; j++) acc[i][j] = 0.f;

    for (int k0 = 0; k0 < K; k0 += 8) {
        float4 av = *(const float4*)(A + (size_t)(rowBase + aRow) * K + k0 + aCol);
        As[aCol + 0][aRow] = av.x;
        As[aCol + 1][aRow] = av.y;
        As[aCol + 2][aRow] = av.z;
        As[aCol + 3][aRow] = av.w;
        float4 bv = *(const float4*)(B + (size_t)(k0 + bRow) * N + colBase + bCol);
        *(float4*)&Bs[bRow][bCol] = bv;
        __syncthreads();

        #pragma unroll
        for (int kk = 0; kk < 8; kk++) {
            float4 a0 = *(float4*)&As[kk][ty * 4];
            float4 a1 = *(float4*)&As[kk][64 + ty * 4];
            float4 b0 = *(float4*)&Bs[kk][tx * 4];
            float4 b1 = *(float4*)&Bs[kk][64 + tx * 4];
            float a[8] = {a0.x, a0.y, a0.z, a0.w, a1.x, a1.y, a1.z, a1.w};
            float bb[8] = {b0.x, b0.y, b0.z, b0.w, b1.x, b1.y, b1.z, b1.w};
            #pragma unroll
            for (int i = 0; i < 8; i++)
                #pragma unroll
                for (int j = 0; j < 8; j++)
                    acc[i][j] += a[i] * bb[j];
        }
        __syncthreads();
    }

    #pragma unroll
    for (int i = 0; i < 8; i++) {
        int r = rowBase + ((i < 4) ? (ty * 4 + i) : (64 + ty * 4 + i - 4));
        #pragma unroll
        for (int half = 0; half < 2; half++) {
            int c = colBase + (half ? (64 + tx * 4) : (tx * 4));
            float4 o;
            o.x = acc[i][half * 4 + 0];
            o.y = acc[i][half * 4 + 1];
            o.z = acc[i][half * 4 + 2];
            o.w = acc[i][half * 4 + 3];
            if (bias) {
                float4 bi = *(const float4*)(bias + c);
                o.x += bi.x; o.y += bi.y; o.z += bi.z; o.w += bi.w;
            }
            *(float4*)(C + (size_t)r * N + c) = o;
        }
    }
}

// ---------------------------------------------------------------------------
// Flash attention with diagonal extra key.
// grid (n/64, H=8, b=4), 256 threads. 64-query tile, 64-key tiles, DH=64.
// Qs/Ks stored transposed [d][row] so both micro-GEMMs read float4 fragments.
// Online-softmax stats (m,l) live in registers, replicated across the 16
// tx-lanes covering a query row, kept consistent via width-16 shfl reductions.
// ---------------------------------------------------------------------------
__global__ __launch_bounds__(256, 2)
void flash_attn(const float* __restrict__ Qp, const float* __restrict__ Kp,
                const float* __restrict__ Vp, const float* __restrict__ XQKp,
                const float* __restrict__ XQVp, float* __restrict__ Op, int n)
{
    extern __shared__ float sm[];
    float* Qs = sm;                 // [d][q]  64*SSTR (Q pre-scaled)
    float* Ks = sm + 64 * SSTR;     // [d][k]  (later: XQK as [d][q])
    float* Vs = sm + 2 * 64 * SSTR; // [k][d]  (later: XQV as [q][d])
    float* Ps = sm + 3 * 64 * SSTR; // [k][q]

    const int tid = threadIdx.x;
    const int tx = tid & 15;
    const int ty = tid >> 4;
    const int h = blockIdx.y;
    const int b = blockIdx.z;
    const int q0 = blockIdx.x * 64;
    const size_t base = ((size_t)b * n) * 512 + (size_t)h * 64;
    const float scale = 0.125f;  // DH^-0.5 = 1/8

    // Load Q tile (scaled, transposed)
    #pragma unroll
    for (int i = 0; i < 4; i++) {
        int f4 = tid + i * 256;
        int row = f4 >> 4;
        int col = (f4 & 15) << 2;
        float4 v = *(const float4*)(Qp + base + (size_t)(q0 + row) * 512 + col);
        Qs[(col + 0) * SSTR + row] = v.x * scale;
        Qs[(col + 1) * SSTR + row] = v.y * scale;
        Qs[(col + 2) * SSTR + row] = v.z * scale;
        Qs[(col + 3) * SSTR + row] = v.w * scale;
    }

    float m_i[4], l_i[4], acc[4][4];
    #pragma unroll
    for (int i = 0; i < 4; i++) {
        m_i[i] = -1e30f; l_i[i] = 0.f;
        #pragma unroll
        for (int j = 0; j < 4; j++) acc[i][j] = 0.f;
    }

    for (int k0 = 0; k0 < n; k0 += 64) {
        __syncthreads();  // protect Ks/Vs/Ps from previous iteration's readers
        #pragma unroll
        for (int i = 0; i < 4; i++) {
            int f4 = tid + i * 256;
            int row = f4 >> 4;
            int col = (f4 & 15) << 2;
            float4 kv = *(const float4*)(Kp + base + (size_t)(k0 + row) * 512 + col);
            Ks[(col + 0) * SSTR + row] = kv.x;
            Ks[(col + 1) * SSTR + row] = kv.y;
            Ks[(col + 2) * SSTR + row] = kv.z;
            Ks[(col + 3) * SSTR + row] = kv.w;
            float4 vv = *(const float4*)(Vp + base + (size_t)(k0 + row) * 512 + col);
            *(float4*)(Vs + row * SSTR + col) = vv;
        }
        __syncthreads();

        // S = Qs @ Ks^T : 4x4 micro-tile per thread
        float s[4][4];
        #pragma unroll
        for (int i = 0; i < 4; i++)
            #pragma unroll
            for (int j = 0; j < 4; j++) s[i][j] = 0.f;

        #pragma unroll 8
        for (int d2 = 0; d2 < 64; d2++) {
            float4 a  = *(float4*)(Qs + d2 * SSTR + ty * 4);
            float4 bb = *(float4*)(Ks + d2 * SSTR + tx * 4);
            s[0][0] += a.x * bb.x; s[0][1] += a.x * bb.y; s[0][2] += a.x * bb.z; s[0][3] += a.x * bb.w;
            s[1][0] += a.y * bb.x; s[1][1] += a.y * bb.y; s[1][2] += a.y * bb.z; s[1][3] += a.y * bb.w;
            s[2][0] += a.z * bb.x; s[2][1] += a.z * bb.y; s[2][2] += a.z * bb.z; s[2][3] += a.z * bb.w;
            s[3][0] += a.w * bb.x; s[3][1] += a.w * bb.y; s[3][2] += a.w * bb.z; s[3][3] += a.w * bb.w;
        }

        // Online softmax per query row (row split across 16 tx-lanes)
        #pragma unroll
        for (int i = 0; i < 4; i++) {
            float mx = fmaxf(fmaxf(s[i][0], s[i][1]), fmaxf(s[i][2], s[i][3]));
            #pragma unroll
            for (int off = 8; off; off >>= 1)
                mx = fmaxf(mx, __shfl_xor_sync(0xffffffffu, mx, off, 16));
            float mn = fmaxf(m_i[i], mx);
            float al = __expf(m_i[i] - mn);
            m_i[i] = mn;
            float rs = 0.f;
            #pragma unroll
            for (int j = 0; j < 4; j++) {
                float p = __expf(s[i][j] - mn);
                s[i][j] = p;
                rs += p;
            }
            #pragma unroll
            for (int off = 8; off; off >>= 1)
                rs += __shfl_xor_sync(0xffffffffu, rs, off, 16);
            l_i[i] = l_i[i] * al + rs;
            #pragma unroll
            for (int j = 0; j < 4; j++) acc[i][j] *= al;
        }

        // Write P transposed [k][q] for the PV micro-GEMM
        #pragma unroll
        for (int i = 0; i < 4; i++)
            #pragma unroll
            for (int j = 0; j < 4; j++)
                Ps[(tx * 4 + j) * SSTR + ty * 4 + i] = s[i][j];
        __syncthreads();

        // O += P @ V
        #pragma unroll 8
        for (int k = 0; k < 64; k++) {
            float4 a  = *(float4*)(Ps + k * SSTR + ty * 4);
            float4 bv = *(float4*)(Vs + k * SSTR + tx * 4);
            acc[0][0] += a.x * bv.x; acc[0][1] += a.x * bv.y; acc[0][2] += a.x * bv.z; acc[0][3] += a.x * bv.w;
            acc[1][0] += a.y * bv.x; acc[1][1] += a.y * bv.y; acc[1][2] += a.y * bv.z; acc[1][3] += a.y * bv.w;
            acc[2][0] += a.z * bv.x; acc[2][1] += a.z * bv.y; acc[2][2] += a.z * bv.z; acc[2][3] += a.z * bv.w;
            acc[3][0] += a.w * bv.x; acc[3][1] += a.w * bv.y; acc[3][2] += a.w * bv.z; acc[3][3] += a.w * bv.w;
        }
    }

    // Diagonal term: one extra per-query key with logit dot(Qscaled, XQK[q])
    // and value XQV[q].
    __syncthreads();
    #pragma unroll
    for (int i = 0; i < 4; i++) {
        int f4 = tid + i * 256;
        int row = f4 >> 4;
        int col = (f4 & 15) << 2;
        float4 kk = *(const float4*)(XQKp + base + (size_t)(q0 + row) * 512 + col);
        Ks[(col + 0) * SSTR + row] = kk.x;
        Ks[(col + 1) * SSTR + row] = kk.y;
        Ks[(col + 2) * SSTR + row] = kk.z;
        Ks[(col + 3) * SSTR + row] = kk.w;
        float4 xv = *(const float4*)(XQVp + base + (size_t)(q0 + row) * 512 + col);
        *(float4*)(Vs + row * SSTR + col) = xv;
    }
    __syncthreads();

    float sd[4] = {0.f, 0.f, 0.f, 0.f};
    #pragma unroll 8
    for (int d2 = 0; d2 < 64; d2++) {
        float4 a = *(float4*)(Qs + d2 * SSTR + ty * 4);
        float4 c = *(float4*)(Ks + d2 * SSTR + ty * 4);
        sd[0] += a.x * c.x; sd[1] += a.y * c.y; sd[2] += a.z * c.z; sd[3] += a.w * c.w;
    }

    #pragma unroll
    for (int i = 0; i < 4; i++) {
        float mn = fmaxf(m_i[i], sd[i]);
        float al = __expf(m_i[i] - mn);
        float pd = __expf(sd[i] - mn);
        float linv = 1.f / (l_i[i] * al + pd);
        float4 xv = *(float4*)(Vs + (ty * 4 + i) * SSTR + tx * 4);
        float4 o;
        o.x = (acc[i][0] * al + pd * xv.x) * linv;
        o.y = (acc[i][1] * al + pd * xv.y) * linv;
        o.z = (acc[i][2] * al + pd * xv.z) * linv;
        o.w = (acc[i][3] * al + pd * xv.w) * linv;
        *(float4*)(Op + base + (size_t)(q0 + ty * 4 + i) * 512 + tx * 4) = o;
    }
}

// ---------------------------------------------------------------------------
// Launch
// ---------------------------------------------------------------------------
extern "C" void kernel_launch(void* const* d_in, const int* in_sizes, int n_in,
                              void* d_out, int out_size)
{
    const float* xq = (const float*)d_in[0];
    const float* xk = (const float*)d_in[1];
    const float* xv = (const float*)d_in[2];
    const float* Wq = (const float*)d_in[3];
    const float* Wk = (const float*)d_in[4];
    const float* Wv = (const float*)d_in[5];
    const float* Wo = (const float*)d_in[6];
    const float* bo = (const float*)d_in[7];
    float* out = (float*)d_out;

    const int D = 512;
    const int Mrows = in_sizes[0] / D;      // b * n = 8192
    const int n = Mrows / 4;                 // b = 4 fixed -> n = 2048

    float *Qb, *Kb, *Vb, *XQKb, *XQVb, *AOb;
    cudaGetSymbolAddress((void**)&Qb,   g_Q);
    cudaGetSymbolAddress((void**)&Kb,   g_K);
    cudaGetSymbolAddress((void**)&Vb,   g_V);
    cudaGetSymbolAddress((void**)&XQKb, g_XQK);
    cudaGetSymbolAddress((void**)&XQVb, g_XQV);
    cudaGetSymbolAddress((void**)&AOb,  g_AO);

    dim3 blk(256);
    dim3 gg(D / 128, Mrows / 128);

    gemm_tiled<<<gg, blk>>>(xq, Wq, nullptr, Qb,   Mrows, D, D);
    gemm_tiled<<<gg, blk>>>(xk, Wk, nullptr, Kb,   Mrows, D, D);
    gemm_tiled<<<gg, blk>>>(xv, Wv, nullptr, Vb,   Mrows, D, D);
    gemm_tiled<<<gg, blk>>>(xq, Wk, nullptr, XQKb, Mrows, D, D);
    gemm_tiled<<<gg, blk>>>(xq, Wv, nullptr, XQVb, Mrows, D, D);

    const int smemBytes = 4 * 64 * SSTR * (int)sizeof(float);  // 69632
    cudaFuncSetAttribute(flash_attn, cudaFuncAttributeMaxDynamicSharedMemorySize,
                         smemBytes);
    flash_attn<<<dim3(n / 64, 8, 4), blk, smemBytes>>>(Qb, Kb, Vb, XQKb, XQVb,
                                                       AOb, n);

    gemm_tiled<<<gg, blk>>>(AOb, Wo, bo, out, Mrows, D, D);
}

// round 3
// speedup vs baseline: 1.3338x; 1.3338x over previous
#include <cuda_runtime.h>
#include <cstdint>
#include <cstddef>

// ===========================================================================
// BaseMultiHeadAttention (b=4, n=2048, d=512, H=8, DH=64), fp32 in/out.
//   Round 3: projection GEMMs via mma.sync.m16n8k8.tf32 (sm_80-universal PTX;
//   the harness toolchain emits PTX for plain sm_103, so no tcgen05/'a'
//   features). Inputs pre-rounded with cvt.rna.tf32.f32 for accuracy.
//   Flash attention (SIMT fp32, verified) unchanged except tf32 rounding of
//   its output (feeds the final GEMM).
// ===========================================================================

#define SSTR 68  // flash smem row stride

// -------------------- scratch (device globals; no allocs) ------------------
__device__ float g_Q  [8192 * 512];
__device__ float g_K  [8192 * 512];
__device__ float g_V  [8192 * 512];
__device__ float g_XQK[8192 * 512];
__device__ float g_XQV[8192 * 512];
__device__ float g_AO [8192 * 512];
__device__ float g_XQc[8192 * 512];
__device__ float g_XKc[8192 * 512];
__device__ float g_XVc[8192 * 512];
__device__ float g_WqT[512 * 512];
__device__ float g_WkT[512 * 512];
__device__ float g_WvT[512 * 512];
__device__ float g_WoT[512 * 512];

// -------------------- helpers ----------------------------------------------
__device__ __forceinline__ uint32_t smem_u32(const void* p) {
    uint32_t a;
    asm("{ .reg .u64 t; cvta.to.shared.u64 t, %1; cvt.u32.u64 %0, t; }"
        : "=r"(a) : "l"(p));
    return a;
}

__device__ __forceinline__ float cvt_tf32(float x) {
    float r;
    asm("cvt.rna.tf32.f32 %0, %1;" : "=f"(r) : "f"(x));
    return r;
}

#define CP_ASYNC16(dst, src) \
    asm volatile("cp.async.cg.shared.global [%0], [%1], 16;" \
        :: "r"((uint32_t)(dst)), "l"(src) : "memory")
#define CP_COMMIT() asm volatile("cp.async.commit_group;" ::: "memory")
#define CP_WAIT(n)  asm volatile("cp.async.wait_group %0;" :: "n"(n) : "memory")

// mma.sync m16n8k8 tf32: D(16x8,f32) = A(16x8) * B(8x8) + C
__device__ __forceinline__ void mma_tf32(float* c, const uint32_t* a,
                                         const uint32_t* b) {
    asm volatile(
        "mma.sync.aligned.m16n8k8.row.col.f32.tf32.tf32.f32 "
        "{%0,%1,%2,%3}, {%4,%5,%6,%7}, {%8,%9}, {%0,%1,%2,%3};"
        : "+f"(c[0]), "+f"(c[1]), "+f"(c[2]), "+f"(c[3])
        : "r"(a[0]), "r"(a[1]), "r"(a[2]), "r"(a[3]), "r"(b[0]), "r"(b[1]));
}

// -------------------- tf32 tensor-core GEMM --------------------------------
// C[M,N] = A[M,K] @ Bt[N,K]^T (+bias).  A, Bt pre-rounded to tf32.
// Block 128x128, BK=32, 256 thr (8 warps, 4x2), warp tile 32x64.
static constexpr int GM_KSTR = 40;                     // floats (160B rows)
static constexpr int GM_ABYTES = 128 * GM_KSTR * 4;    // 20480
static constexpr int GM_STAGE = 2 * GM_ABYTES;         // 40960 (A+B)
static constexpr int GM_SMEM = 2 * GM_STAGE;           // 81920

__device__ __forceinline__ void gm_load(float* As, float* Bs,
                                        const float* __restrict__ A,
                                        const float* __restrict__ Bt,
                                        int rowBase, int colBase, int K,
                                        int k0, int tid) {
    uint32_t asb = smem_u32(As);
    uint32_t bsb = smem_u32(Bs);
    #pragma unroll
    for (int i = 0; i < 4; i++) {
        int seg = tid + i * 256;
        int r = seg >> 3;
        int s = seg & 7;
        CP_ASYNC16(asb + (uint32_t)(r * 160 + s * 16),
                   A + (size_t)(rowBase + r) * K + k0 + s * 4);
        CP_ASYNC16(bsb + (uint32_t)(r * 160 + s * 16),
                   Bt + (size_t)(colBase + r) * K + k0 + s * 4);
    }
}

__global__ __launch_bounds__(256, 2)
void gemm_mma(const float* __restrict__ A, const float* __restrict__ Bt,
              const float* __restrict__ bias, float* __restrict__ C,
              int M, int N, int K)
{
    extern __shared__ float gsm[];

    const int tid = threadIdx.x;
    const int wid = tid >> 5;
    const int lane = tid & 31;
    const int g = lane >> 2;    // group id (row within fragment)
    const int cc = lane & 3;    // thread in group (col within fragment)
    const int wm = wid >> 1;    // 0..3
    const int wn = wid & 1;     // 0..1
    const int rowBase = blockIdx.y * 128;
    const int colBase = blockIdx.x * 128;
    const int CH = K / 32;      // 16

    float acc[2][8][4];
    #pragma unroll
    for (int mf = 0; mf < 2; mf++)
        #pragma unroll
        for (int nf = 0; nf < 8; nf++)
            #pragma unroll
            for (int q = 0; q < 4; q++) acc[mf][nf][q] = 0.f;

    // prologue
    gm_load(gsm, gsm + 128 * GM_KSTR, A, Bt, rowBase, colBase, K, 0, tid);
    CP_COMMIT();

    for (int c = 0; c < CH; c++) {
        float* As = gsm + (c & 1) * (2 * 128 * GM_KSTR);
        float* Bs = As + 128 * GM_KSTR;
        if (c + 1 < CH) {
            float* Asn = gsm + ((c + 1) & 1) * (2 * 128 * GM_KSTR);
            gm_load(Asn, Asn + 128 * GM_KSTR, A, Bt, rowBase, colBase, K,
                    (c + 1) * 32, tid);
            CP_COMMIT();
            CP_WAIT(1);
        } else {
            CP_WAIT(0);
        }
        __syncthreads();

        #pragma unroll
        for (int t = 0; t < 4; t++) {
            const int k0 = t * 8;
            uint32_t a[2][4];
            #pragma unroll
            for (int mf = 0; mf < 2; mf++) {
                int r0 = wm * 32 + mf * 16 + g;
                a[mf][0] = __float_as_uint(As[r0 * GM_KSTR + k0 + cc]);
                a[mf][1] = __float_as_uint(As[(r0 + 8) * GM_KSTR + k0 + cc]);
                a[mf][2] = __float_as_uint(As[r0 * GM_KSTR + k0 + cc + 4]);
                a[mf][3] = __float_as_uint(As[(r0 + 8) * GM_KSTR + k0 + cc + 4]);
            }
            #pragma unroll
            for (int nf = 0; nf < 8; nf++) {
                int nr = wn * 64 + nf * 8 + g;
                uint32_t b[2];
                b[0] = __float_as_uint(Bs[nr * GM_KSTR + k0 + cc]);
                b[1] = __float_as_uint(Bs[nr * GM_KSTR + k0 + cc + 4]);
                mma_tf32(acc[0][nf], a[0], b);
                mma_tf32(acc[1][nf], a[1], b);
            }
        }
        __syncthreads();
    }

    // epilogue
    #pragma unroll
    for (int mf = 0; mf < 2; mf++) {
        int r0 = rowBase + wm * 32 + mf * 16 + g;
        #pragma unroll
        for (int nf = 0; nf < 8; nf++) {
            int col = colBase + wn * 64 + nf * 8 + 2 * cc;
            float2 v0 = make_float2(acc[mf][nf][0], acc[mf][nf][1]);
            float2 v1 = make_float2(acc[mf][nf][2], acc[mf][nf][3]);
            if (bias) {
                float2 bi = *(const float2*)(bias + col);
                v0.x += bi.x; v0.y += bi.y;
                v1.x += bi.x; v1.y += bi.y;
            }
            *(float2*)(C + (size_t)r0 * N + col) = v0;
            *(float2*)(C + (size_t)(r0 + 8) * N + col) = v1;
        }
    }
}

// -------------------- tf32 rounding copy -----------------------------------
__global__ __launch_bounds__(256, 8)
void cvt_tf32_copy(const float* __restrict__ in, float* __restrict__ out)
{
    size_t i = ((size_t)blockIdx.x * 256 + threadIdx.x) * 4;
    float4 v = *(const float4*)(in + i);
    v.x = cvt_tf32(v.x); v.y = cvt_tf32(v.y);
    v.z = cvt_tf32(v.z); v.w = cvt_tf32(v.w);
    *(float4*)(out + i) = v;
}

// -------------------- 512x512 transpose + tf32 round -----------------------
__global__ __launch_bounds__(256, 4)
void transpose512_cvt(const float* __restrict__ in, float* __restrict__ out)
{
    __shared__ float t[32][33];
    int bx = blockIdx.x * 32, by = blockIdx.y * 32;
    int x = threadIdx.x, y4 = threadIdx.y * 4;
    #pragma unroll
    for (int i = 0; i < 4; i++)
        t[y4 + i][x] = in[(size_t)(by + y4 + i) * 512 + bx + x];
    __syncthreads();
    #pragma unroll
    for (int i = 0; i < 4; i++)
        out[(size_t)(bx + y4 + i) * 512 + by + x] = cvt_tf32(t[x][y4 + i]);
}

// -------------------- flash attention (fp32 SIMT, verified R1) -------------
__global__ __launch_bounds__(256, 2)
void flash_attn(const float* __restrict__ Qp, const float* __restrict__ Kp,
                const float* __restrict__ Vp, const float* __restrict__ XQKp,
                const float* __restrict__ XQVp, float* __restrict__ Op, int n)
{
    extern __shared__ float sm[];
    float* Qs = sm;                 // [d][q]
    float* Ks = sm + 64 * SSTR;     // [d][k]
    float* Vs = sm + 2 * 64 * SSTR; // [k][d]
    float* Ps = sm + 3 * 64 * SSTR; // [k][q]

    const int tid = threadIdx.x;
    const int tx = tid & 15;
    const int ty = tid >> 4;
    const int h = blockIdx.y;
    const int b = blockIdx.z;
    const int q0 = blockIdx.x * 64;
    const size_t base = ((size_t)b * n) * 512 + (size_t)h * 64;
    const float scale = 0.125f;

    #pragma unroll
    for (int i = 0; i < 4; i++) {
        int f4 = tid + i * 256;
        int row = f4 >> 4;
        int col = (f4 & 15) << 2;
        float4 v = *(const float4*)(Qp + base + (size_t)(q0 + row) * 512 + col);
        Qs[(col + 0) * SSTR + row] = v.x * scale;
        Qs[(col + 1) * SSTR + row] = v.y * scale;
        Qs[(col + 2) * SSTR + row] = v.z * scale;
        Qs[(col + 3) * SSTR + row] = v.w * scale;
    }

    float m_i[4], l_i[4], acc[4][4];
    #pragma unroll
    for (int i = 0; i < 4; i++) {
        m_i[i] = -1e30f; l_i[i] = 0.f;
        #pragma unroll
        for (int j = 0; j < 4; j++) acc[i][j] = 0.f;
    }

    for (int k0 = 0; k0 < n; k0 += 64) {
        __syncthreads();
        #pragma unroll
        for (int i = 0; i < 4; i++) {
            int f4 = tid + i * 256;
            int row = f4 >> 4;
            int col = (f4 & 15) << 2;
            float4 kv = *(const float4*)(Kp + base + (size_t)(k0 + row) * 512 + col);
            Ks[(col + 0) * SSTR + row] = kv.x;
            Ks[(col + 1) * SSTR + row] = kv.y;
            Ks[(col + 2) * SSTR + row] = kv.z;
            Ks[(col + 3) * SSTR + row] = kv.w;
            float4 vv = *(const float4*)(Vp + base + (size_t)(k0 + row) * 512 + col);
            *(float4*)(Vs + row * SSTR + col) = vv;
        }
        __syncthreads();

        float s[4][4];
        #pragma unroll
        for (int i = 0; i < 4; i++)
            #pragma unroll
            for (int j = 0; j < 4; j++) s[i][j] = 0.f;

        #pragma unroll 8
        for (int d2 = 0; d2 < 64; d2++) {
            float4 a  = *(float4*)(Qs + d2 * SSTR + ty * 4);
            float4 bb = *(float4*)(Ks + d2 * SSTR + tx * 4);
            s[0][0] += a.x * bb.x; s[0][1] += a.x * bb.y; s[0][2] += a.x * bb.z; s[0][3] += a.x * bb.w;
            s[1][0] += a.y * bb.x; s[1][1] += a.y * bb.y; s[1][2] += a.y * bb.z; s[1][3] += a.y * bb.w;
            s[2][0] += a.z * bb.x; s[2][1] += a.z * bb.y; s[2][2] += a.z * bb.z; s[2][3] += a.z * bb.w;
            s[3][0] += a.w * bb.x; s[3][1] += a.w * bb.y; s[3][2] += a.w * bb.z; s[3][3] += a.w * bb.w;
        }

        #pragma unroll
        for (int i = 0; i < 4; i++) {
            float mx = fmaxf(fmaxf(s[i][0], s[i][1]), fmaxf(s[i][2], s[i][3]));
            #pragma unroll
            for (int off = 8; off; off >>= 1)
                mx = fmaxf(mx, __shfl_xor_sync(0xffffffffu, mx, off, 16));
            float mn = fmaxf(m_i[i], mx);
            float al = __expf(m_i[i] - mn);
            m_i[i] = mn;
            float rs = 0.f;
            #pragma unroll
            for (int j = 0; j < 4; j++) {
                float p = __expf(s[i][j] - mn);
                s[i][j] = p;
                rs += p;
            }
            #pragma unroll
            for (int off = 8; off; off >>= 1)
                rs += __shfl_xor_sync(0xffffffffu, rs, off, 16);
            l_i[i] = l_i[i] * al + rs;
            #pragma unroll
            for (int j = 0; j < 4; j++) acc[i][j] *= al;
        }

        #pragma unroll
        for (int i = 0; i < 4; i++)
            #pragma unroll
            for (int j = 0; j < 4; j++)
                Ps[(tx * 4 + j) * SSTR + ty * 4 + i] = s[i][j];
        __syncthreads();

        #pragma unroll 8
        for (int k = 0; k < 64; k++) {
            float4 a  = *(float4*)(Ps + k * SSTR + ty * 4);
            float4 bv = *(float4*)(Vs + k * SSTR + tx * 4);
            acc[0][0] += a.x * bv.x; acc[0][1] += a.x * bv.y; acc[0][2] += a.x * bv.z; acc[0][3] += a.x * bv.w;
            acc[1][0] += a.y * bv.x; acc[1][1] += a.y * bv.y; acc[1][2] += a.y * bv.z; acc[1][3] += a.y * bv.w;
            acc[2][0] += a.z * bv.x; acc[2][1] += a.z * bv.y; acc[2][2] += a.z * bv.z; acc[2][3] += a.z * bv.w;
            acc[3][0] += a.w * bv.x; acc[3][1] += a.w * bv.y; acc[3][2] += a.w * bv.z; acc[3][3] += a.w * bv.w;
        }
    }

    __syncthreads();
    #pragma unroll
    for (int i = 0; i < 4; i++) {
        int f4 = tid + i * 256;
        int row = f4 >> 4;
        int col = (f4 & 15) << 2;
        float4 kk = *(const float4*)(XQKp + base + (size_t)(q0 + row) * 512 + col);
        Ks[(col + 0) * SSTR + row] = kk.x;
        Ks[(col + 1) * SSTR + row] = kk.y;
        Ks[(col + 2) * SSTR + row] = kk.z;
        Ks[(col + 3) * SSTR + row] = kk.w;
        float4 xv = *(const float4*)(XQVp + base + (size_t)(q0 + row) * 512 + col);
        *(float4*)(Vs + row * SSTR + col) = xv;
    }
    __syncthreads();

    float sd[4] = {0.f, 0.f, 0.f, 0.f};
    #pragma unroll 8
    for (int d2 = 0; d2 < 64; d2++) {
        float4 a = *(float4*)(Qs + d2 * SSTR + ty * 4);
        float4 c = *(float4*)(Ks + d2 * SSTR + ty * 4);
        sd[0] += a.x * c.x; sd[1] += a.y * c.y; sd[2] += a.z * c.z; sd[3] += a.w * c.w;
    }

    #pragma unroll
    for (int i = 0; i < 4; i++) {
        float mn = fmaxf(m_i[i], sd[i]);
        float al = __expf(m_i[i] - mn);
        float pd = __expf(sd[i] - mn);
        float linv = 1.f / (l_i[i] * al + pd);
        float4 xv = *(float4*)(Vs + (ty * 4 + i) * SSTR + tx * 4);
        float4 o;
        // tf32-round the output: it feeds the final tensor-core GEMM.
        o.x = cvt_tf32((acc[i][0] * al + pd * xv.x) * linv);
        o.y = cvt_tf32((acc[i][1] * al + pd * xv.y) * linv);
        o.z = cvt_tf32((acc[i][2] * al + pd * xv.z) * linv);
        o.w = cvt_tf32((acc[i][3] * al + pd * xv.w) * linv);
        *(float4*)(Op + base + (size_t)(q0 + ty * 4 + i) * 512 + tx * 4) = o;
    }
}

// -------------------- launch -----------------------------------------------
extern "C" void kernel_launch(void* const* d_in, const int* in_sizes, int n_in,
                              void* d_out, int out_size)
{
    const float* xq = (const float*)d_in[0];
    const float* xk = (const float*)d_in[1];
    const float* xv = (const float*)d_in[2];
    const float* Wq = (const float*)d_in[3];
    const float* Wk = (const float*)d_in[4];
    const float* Wv = (const float*)d_in[5];
    const float* Wo = (const float*)d_in[6];
    const float* bo = (const float*)d_in[7];
    float* out = (float*)d_out;

    const int D = 512;
    const int Mrows = in_sizes[0] / D;      // 8192
    const int n = Mrows / 4;                 // 2048

    float *Qb, *Kb, *Vb, *XQKb, *XQVb, *AOb;
    float *XQc, *XKc, *XVc, *WqT, *WkT, *WvT, *WoT;
    cudaGetSymbolAddress((void**)&Qb,   g_Q);
    cudaGetSymbolAddress((void**)&Kb,   g_K);
    cudaGetSymbolAddress((void**)&Vb,   g_V);
    cudaGetSymbolAddress((void**)&XQKb, g_XQK);
    cudaGetSymbolAddress((void**)&XQVb, g_XQV);
    cudaGetSymbolAddress((void**)&AOb,  g_AO);
    cudaGetSymbolAddress((void**)&XQc,  g_XQc);
    cudaGetSymbolAddress((void**)&XKc,  g_XKc);
    cudaGetSymbolAddress((void**)&XVc,  g_XVc);
    cudaGetSymbolAddress((void**)&WqT,  g_WqT);
    cudaGetSymbolAddress((void**)&WkT,  g_WkT);
    cudaGetSymbolAddress((void**)&WvT,  g_WvT);
    cudaGetSymbolAddress((void**)&WoT,  g_WoT);

    // tf32-round activations + transpose/round weights
    const int cvtBlocks = (Mrows * D) / (256 * 4);  // 4096
    cvt_tf32_copy<<<cvtBlocks, 256>>>(xq, XQc);
    cvt_tf32_copy<<<cvtBlocks, 256>>>(xk, XKc);
    cvt_tf32_copy<<<cvtBlocks, 256>>>(xv, XVc);
    dim3 tb(32, 8), tg(16, 16);
    transpose512_cvt<<<tg, tb>>>(Wq, WqT);
    transpose512_cvt<<<tg, tb>>>(Wk, WkT);
    transpose512_cvt<<<tg, tb>>>(Wv, WvT);
    transpose512_cvt<<<tg, tb>>>(Wo, WoT);

    cudaFuncSetAttribute(gemm_mma, cudaFuncAttributeMaxDynamicSharedMemorySize,
                         GM_SMEM);
    dim3 gg(D / 128, Mrows / 128);  // (4, 64)
    gemm_mma<<<gg, 256, GM_SMEM>>>(XQc, WqT, nullptr, Qb,   Mrows, D, D);
    gemm_mma<<<gg, 256, GM_SMEM>>>(XKc, WkT, nullptr, Kb,   Mrows, D, D);
    gemm_mma<<<gg, 256, GM_SMEM>>>(XVc, WvT, nullptr, Vb,   Mrows, D, D);
    gemm_mma<<<gg, 256, GM_SMEM>>>(XQc, WkT, nullptr, XQKb, Mrows, D, D);
    gemm_mma<<<gg, 256, GM_SMEM>>>(XQc, WvT, nullptr, XQVb, Mrows, D, D);

    const int smemBytes = 4 * 64 * SSTR * (int)sizeof(float);
    cudaFuncSetAttribute(flash_attn, cudaFuncAttributeMaxDynamicSharedMemorySize,
                         smemBytes);
    flash_attn<<<dim3(n / 64, 8, 4), 256, smemBytes>>>(Qb, Kb, Vb, XQKb, XQVb,
                                                       AOb, n);

    gemm_mma<<<gg, 256, GM_SMEM>>>(AOb, WoT, bo, out, Mrows, D, D);
}

// round 4
// speedup vs baseline: 3.5298x; 2.6464x over previous
#include <cuda_runtime.h>
#include <cuda_fp16.h>
#include <cstdint>
#include <cstddef>

// ===========================================================================
// BaseMultiHeadAttention (b=4, n=2048, d=512, H=8, DH=64), fp32 in/out.
//   Round 4: flash attention on tensor cores.
//     QK^T : mma.sync.m16n8k8.tf32 (Q,K tf32-rounded in gemm epilogue)
//     PV   : mma.sync.m16n8k16.f16 (P packed in-register, V pre-packed half2)
//   Projections: mma.sync tf32 GEMM (round 3, verified).
// ===========================================================================

// -------------------- scratch (device globals; no allocs) ------------------
__device__ float g_Q  [8192 * 512];
__device__ float g_K  [8192 * 512];
__device__ float g_V  [8192 * 512];
__device__ float g_XQK[8192 * 512];
__device__ float g_XQV[8192 * 512];
__device__ float g_AO [8192 * 512];
__device__ float g_XQc[8192 * 512];
__device__ float g_XKc[8192 * 512];
__device__ float g_XVc[8192 * 512];
__device__ float g_WqT[512 * 512];
__device__ float g_WkT[512 * 512];
__device__ float g_WvT[512 * 512];
__device__ float g_WoT[512 * 512];
__device__ uint32_t g_Vh[4 * 8 * 1024 * 64];  // [b*8+h][key/2][dim] half2

// -------------------- helpers ----------------------------------------------
__device__ __forceinline__ uint32_t smem_u32(const void* p) {
    uint32_t a;
    asm("{ .reg .u64 t; cvta.to.shared.u64 t, %1; cvt.u32.u64 %0, t; }"
        : "=r"(a) : "l"(p));
    return a;
}

__device__ __forceinline__ float cvt_tf32(float x) {
    float r;
    asm("cvt.rna.tf32.f32 %0, %1;" : "=f"(r) : "f"(x));
    return r;
}

__device__ __forceinline__ uint32_t pack_h2(float x, float y) {
    __half2 h = __floats2half2_rn(x, y);
    return *(uint32_t*)&h;
}

#define CP_ASYNC16(dst, src) \
    asm volatile("cp.async.cg.shared.global [%0], [%1], 16;" \
        :: "r"((uint32_t)(dst)), "l"(src) : "memory")
#define CP_COMMIT() asm volatile("cp.async.commit_group;" ::: "memory")
#define CP_WAIT(n)  asm volatile("cp.async.wait_group %0;" :: "n"(n) : "memory")

// D(16x8,f32) += A(16x8 tf32) * B(8x8 tf32)
__device__ __forceinline__ void mma_tf32(float* c, const uint32_t* a,
                                         uint32_t b0, uint32_t b1) {
    asm volatile(
        "mma.sync.aligned.m16n8k8.row.col.f32.tf32.tf32.f32 "
        "{%0,%1,%2,%3}, {%4,%5,%6,%7}, {%8,%9}, {%0,%1,%2,%3};"
        : "+f"(c[0]), "+f"(c[1]), "+f"(c[2]), "+f"(c[3])
        : "r"(a[0]), "r"(a[1]), "r"(a[2]), "r"(a[3]), "r"(b0), "r"(b1));
}

// D(16x8,f32) += A(16x16 f16) * B(16x8 f16)
__device__ __forceinline__ void mma_f16(float* c, const uint32_t* a,
                                        uint32_t b0, uint32_t b1) {
    asm volatile(
        "mma.sync.aligned.m16n8k16.row.col.f32.f16.f16.f32 "
        "{%0,%1,%2,%3}, {%4,%5,%6,%7}, {%8,%9}, {%0,%1,%2,%3};"
        : "+f"(c[0]), "+f"(c[1]), "+f"(c[2]), "+f"(c[3])
        : "r"(a[0]), "r"(a[1]), "r"(a[2]), "r"(a[3]), "r"(b0), "r"(b1));
}

// -------------------- tf32 tensor-core GEMM (round 3) ----------------------
static constexpr int GM_KSTR = 40;
static constexpr int GM_SMEM = 2 * 2 * 128 * GM_KSTR * 4;  // 81920

__device__ __forceinline__ void gm_load(float* As, float* Bs,
                                        const float* __restrict__ A,
                                        const float* __restrict__ Bt,
                                        int rowBase, int colBase, int K,
                                        int k0, int tid) {
    uint32_t asb = smem_u32(As);
    uint32_t bsb = smem_u32(Bs);
    #pragma unroll
    for (int i = 0; i < 4; i++) {
        int seg = tid + i * 256;
        int r = seg >> 3;
        int s = seg & 7;
        CP_ASYNC16(asb + (uint32_t)(r * 160 + s * 16),
                   A + (size_t)(rowBase + r) * K + k0 + s * 4);
        CP_ASYNC16(bsb + (uint32_t)(r * 160 + s * 16),
                   Bt + (size_t)(colBase + r) * K + k0 + s * 4);
    }
}

__global__ __launch_bounds__(256, 2)
void gemm_mma(const float* __restrict__ A, const float* __restrict__ Bt,
              const float* __restrict__ bias, float* __restrict__ C,
              int M, int N, int K, int rnd)
{
    extern __shared__ float gsm[];

    const int tid = threadIdx.x;
    const int wid = tid >> 5;
    const int lane = tid & 31;
    const int g = lane >> 2;
    const int cc = lane & 3;
    const int wm = wid >> 1;
    const int wn = wid & 1;
    const int rowBase = blockIdx.y * 128;
    const int colBase = blockIdx.x * 128;
    const int CH = K / 32;

    float acc[2][8][4];
    #pragma unroll
    for (int mf = 0; mf < 2; mf++)
        #pragma unroll
        for (int nf = 0; nf < 8; nf++)
            #pragma unroll
            for (int q = 0; q < 4; q++) acc[mf][nf][q] = 0.f;

    gm_load(gsm, gsm + 128 * GM_KSTR, A, Bt, rowBase, colBase, K, 0, tid);
    CP_COMMIT();

    for (int c = 0; c < CH; c++) {
        float* As = gsm + (c & 1) * (2 * 128 * GM_KSTR);
        float* Bs = As + 128 * GM_KSTR;
        if (c + 1 < CH) {
            float* Asn = gsm + ((c + 1) & 1) * (2 * 128 * GM_KSTR);
            gm_load(Asn, Asn + 128 * GM_KSTR, A, Bt, rowBase, colBase, K,
                    (c + 1) * 32, tid);
            CP_COMMIT();
            CP_WAIT(1);
        } else {
            CP_WAIT(0);
        }
        __syncthreads();

        #pragma unroll
        for (int t = 0; t < 4; t++) {
            const int k0 = t * 8;
            uint32_t a[2][4];
            #pragma unroll
            for (int mf = 0; mf < 2; mf++) {
                int r0 = wm * 32 + mf * 16 + g;
                a[mf][0] = __float_as_uint(As[r0 * GM_KSTR + k0 + cc]);
                a[mf][1] = __float_as_uint(As[(r0 + 8) * GM_KSTR + k0 + cc]);
                a[mf][2] = __float_as_uint(As[r0 * GM_KSTR + k0 + cc + 4]);
                a[mf][3] = __float_as_uint(As[(r0 + 8) * GM_KSTR + k0 + cc + 4]);
            }
            #pragma unroll
            for (int nf = 0; nf < 8; nf++) {
                int nr = wn * 64 + nf * 8 + g;
                uint32_t b0 = __float_as_uint(Bs[nr * GM_KSTR + k0 + cc]);
                uint32_t b1 = __float_as_uint(Bs[nr * GM_KSTR + k0 + cc + 4]);
                mma_tf32(acc[0][nf], a[0], b0, b1);
                mma_tf32(acc[1][nf], a[1], b0, b1);
            }
        }
        __syncthreads();
    }

    #pragma unroll
    for (int mf = 0; mf < 2; mf++) {
        int r0 = rowBase + wm * 32 + mf * 16 + g;
        #pragma unroll
        for (int nf = 0; nf < 8; nf++) {
            int col = colBase + wn * 64 + nf * 8 + 2 * cc;
            float2 v0 = make_float2(acc[mf][nf][0], acc[mf][nf][1]);
            float2 v1 = make_float2(acc[mf][nf][2], acc[mf][nf][3]);
            if (bias) {
                float2 bi = *(const float2*)(bias + col);
                v0.x += bi.x; v0.y += bi.y;
                v1.x += bi.x; v1.y += bi.y;
            }
            if (rnd) {
                v0.x = cvt_tf32(v0.x); v0.y = cvt_tf32(v0.y);
                v1.x = cvt_tf32(v1.x); v1.y = cvt_tf32(v1.y);
            }
            *(float2*)(C + (size_t)r0 * N + col) = v0;
            *(float2*)(C + (size_t)(r0 + 8) * N + col) = v1;
        }
    }
}

// -------------------- small prep kernels -----------------------------------
__global__ __launch_bounds__(256, 8)
void cvt_tf32_copy(const float* __restrict__ in, float* __restrict__ out)
{
    size_t i = ((size_t)blockIdx.x * 256 + threadIdx.x) * 4;
    float4 v = *(const float4*)(in + i);
    v.x = cvt_tf32(v.x); v.y = cvt_tf32(v.y);
    v.z = cvt_tf32(v.z); v.w = cvt_tf32(v.w);
    *(float4*)(out + i) = v;
}

__global__ __launch_bounds__(256, 4)
void transpose512_cvt(const float* __restrict__ in, float* __restrict__ out)
{
    __shared__ float t[32][33];
    int bx = blockIdx.x * 32, by = blockIdx.y * 32;
    int x = threadIdx.x, y4 = threadIdx.y * 4;
    #pragma unroll
    for (int i = 0; i < 4; i++)
        t[y4 + i][x] = in[(size_t)(by + y4 + i) * 512 + bx + x];
    __syncthreads();
    #pragma unroll
    for (int i = 0; i < 4; i++)
        out[(size_t)(bx + y4 + i) * 512 + by + x] = cvt_tf32(t[x][y4 + i]);
}

// V[b,key,512] fp32 -> Vh[b*8+h][key/2][64] half2 (pair over adjacent keys)
__global__ __launch_bounds__(256, 8)
void conv_v_half(const float* __restrict__ V, uint32_t* __restrict__ Vh, int n)
{
    int idx = blockIdx.x * 256 + threadIdx.x;   // [bh][k2][dim]
    int dim = idx & 63;
    int k2  = (idx >> 6) & (1024 - 1);
    int bh  = idx >> 16;
    int b = bh >> 3, h = bh & 7;
    size_t src = ((size_t)b * n + 2 * k2) * 512 + h * 64 + dim;
    Vh[idx] = pack_h2(V[src], V[src + 512]);
}

// -------------------- flash attention on tensor cores ----------------------
// grid (n/128, 8, 4), 256 thr (8 warps x 16 query rows). Key tiles of 64.
static constexpr int FKS = 68;                 // smem row stride (floats/half2)
static constexpr int FA_QS_OFF = 0;            // 128x68 fp32 (Q, later XQV)
static constexpr int FA_KS_OFF = 128 * FKS;    // 2 stages x 64x68 fp32 (K, later XQK)
static constexpr int FA_VH_OFF = 256 * FKS;    // 2 stages x 32x68 half2
static constexpr int FA_SMEM = (256 * FKS + 64 * FKS) * 4;  // 87040 B

__global__ __launch_bounds__(256, 1)
void flash_attn_mma(const float* __restrict__ Qp, const float* __restrict__ Kp,
                    const uint32_t* __restrict__ Vhp,
                    const float* __restrict__ XQKp,
                    const float* __restrict__ XQVp,
                    float* __restrict__ Op, int n)
{
    extern __shared__ float sm[];
    float*    Qs = sm + FA_QS_OFF;
    float*    Ks = sm + FA_KS_OFF;
    uint32_t* Vh = (uint32_t*)(sm + FA_VH_OFF);
    const uint32_t ksU = smem_u32(Ks);
    const uint32_t vhU = smem_u32(Vh);

    const int tid = threadIdx.x;
    const int w = tid >> 5;
    const int lane = tid & 31;
    const int g = lane >> 2;
    const int cc = lane & 3;
    const int h = blockIdx.y;
    const int b = blockIdx.z;
    const int q0 = blockIdx.x * 128;
    const size_t base = ((size_t)b * n) * 512 + (size_t)h * 64;
    const size_t vbase = ((size_t)(b * 8 + h)) * (n / 2) * 64;
    const int NT = n / 64;  // 32
    const int r0 = w * 16 + g;

    // ---- stage Q tile (scaled by DH^-0.5 = 1/8; scale is exact in tf32) ----
    #pragma unroll
    for (int i = 0; i < 8; i++) {
        int f4 = tid + i * 256;
        int row = f4 >> 4;
        int s = (f4 & 15) << 2;
        float4 v = *(const float4*)(Qp + base + (size_t)(q0 + row) * 512 + s);
        v.x *= 0.125f; v.y *= 0.125f; v.z *= 0.125f; v.w *= 0.125f;
        *(float4*)&Qs[row * FKS + s] = v;
    }
    __syncthreads();

    // Q fragments resident in registers for the whole kernel
    uint32_t qa[8][4];
    #pragma unroll
    for (int t = 0; t < 8; t++) {
        qa[t][0] = __float_as_uint(Qs[r0 * FKS + 8 * t + cc]);
        qa[t][1] = __float_as_uint(Qs[(r0 + 8) * FKS + 8 * t + cc]);
        qa[t][2] = __float_as_uint(Qs[r0 * FKS + 8 * t + cc + 4]);
        qa[t][3] = __float_as_uint(Qs[(r0 + 8) * FKS + 8 * t + cc + 4]);
    }

    // ---- K/V tile loaders (cp.async) ----
    auto loadTile = [&](int t, int stage) {
        int key0 = t * 64;
        // K: 64 rows x 256B
        #pragma unroll
        for (int i = 0; i < 4; i++) {
            int seg = tid + i * 256;
            int r = seg >> 4;
            int s = seg & 15;
            CP_ASYNC16(ksU + (uint32_t)(stage * 64 * FKS + r * FKS + s * 4) * 4,
                       Kp + base + (size_t)(key0 + r) * 512 + s * 4);
        }
        // Vh: 32 rows x 256B
        #pragma unroll
        for (int i = 0; i < 2; i++) {
            int seg = tid + i * 256;
            int r = seg >> 4;
            int s = seg & 15;
            CP_ASYNC16(vhU + (uint32_t)(stage * 32 * FKS + r * FKS + s * 4) * 4,
                       Vhp + vbase + (size_t)(key0 / 2 + r) * 64 + s * 4);
        }
    };

    loadTile(0, 0); CP_COMMIT();
    loadTile(1, 1); CP_COMMIT();

    float m0 = -1e30f, m1 = -1e30f, l0 = 0.f, l1 = 0.f;
    float o[8][4];
    #pragma unroll
    for (int nf = 0; nf < 8; nf++)
        #pragma unroll
        for (int q = 0; q < 4; q++) o[nf][q] = 0.f;

    for (int t = 0; t < NT; t++) {
        if (t + 1 < NT) CP_WAIT(1); else CP_WAIT(0);
        __syncthreads();
        float*    Kst = Ks + (t & 1) * 64 * FKS;
        uint32_t* Vst = Vh + (t & 1) * 32 * FKS;

        // S = Qs @ K^T  (16x64 per warp)
        float s[8][4];
        #pragma unroll
        for (int nf = 0; nf < 8; nf++)
            #pragma unroll
            for (int q = 0; q < 4; q++) s[nf][q] = 0.f;

        #pragma unroll
        for (int kt = 0; kt < 8; kt++) {
            #pragma unroll
            for (int nf = 0; nf < 8; nf++) {
                const float* kr = Kst + (8 * nf + g) * FKS + 8 * kt + cc;
                mma_tf32(s[nf], qa[kt], __float_as_uint(kr[0]),
                         __float_as_uint(kr[4]));
            }
        }

        // online softmax (rows r0, r0+8; 16 cols per thread, 4 lanes/row)
        float mx0 = s[0][0], mx1 = s[0][2];
        #pragma unroll
        for (int nf = 0; nf < 8; nf++) {
            mx0 = fmaxf(mx0, fmaxf(s[nf][0], s[nf][1]));
            mx1 = fmaxf(mx1, fmaxf(s[nf][2], s[nf][3]));
        }
        mx0 = fmaxf(mx0, __shfl_xor_sync(0xffffffffu, mx0, 1));
        mx0 = fmaxf(mx0, __shfl_xor_sync(0xffffffffu, mx0, 2));
        mx1 = fmaxf(mx1, __shfl_xor_sync(0xffffffffu, mx1, 1));
        mx1 = fmaxf(mx1, __shfl_xor_sync(0xffffffffu, mx1, 2));
        float mn0 = fmaxf(m0, mx0), mn1 = fmaxf(m1, mx1);
        float al0 = __expf(m0 - mn0), al1 = __expf(m1 - mn1);
        m0 = mn0; m1 = mn1;
        float rs0 = 0.f, rs1 = 0.f;
        #pragma unroll
        for (int nf = 0; nf < 8; nf++) {
            s[nf][0] = __expf(s[nf][0] - mn0);
            s[nf][1] = __expf(s[nf][1] - mn0);
            s[nf][2] = __expf(s[nf][2] - mn1);
            s[nf][3] = __expf(s[nf][3] - mn1);
            rs0 += s[nf][0] + s[nf][1];
            rs1 += s[nf][2] + s[nf][3];
        }
        rs0 += __shfl_xor_sync(0xffffffffu, rs0, 1);
        rs0 += __shfl_xor_sync(0xffffffffu, rs0, 2);
        rs1 += __shfl_xor_sync(0xffffffffu, rs1, 1);
        rs1 += __shfl_xor_sync(0xffffffffu, rs1, 2);
        l0 = l0 * al0 + rs0;
        l1 = l1 * al1 + rs1;
        #pragma unroll
        for (int nf = 0; nf < 8; nf++) {
            o[nf][0] *= al0; o[nf][1] *= al0;
            o[nf][2] *= al1; o[nf][3] *= al1;
        }

        // pack P to fp16 A-fragments (k=16 chunks), all in registers
        uint32_t pa[4][4];
        #pragma unroll
        for (int kc = 0; kc < 4; kc++) {
            pa[kc][0] = pack_h2(s[2 * kc][0], s[2 * kc][1]);
            pa[kc][1] = pack_h2(s[2 * kc][2], s[2 * kc][3]);
            pa[kc][2] = pack_h2(s[2 * kc + 1][0], s[2 * kc + 1][1]);
            pa[kc][3] = pack_h2(s[2 * kc + 1][2], s[2 * kc + 1][3]);
        }

        // O += P @ V
        #pragma unroll
        for (int kc = 0; kc < 4; kc++) {
            #pragma unroll
            for (int nf = 0; nf < 8; nf++) {
                uint32_t b0 = Vst[(8 * kc + cc) * FKS + 8 * nf + g];
                uint32_t b1 = Vst[(8 * kc + cc + 4) * FKS + 8 * nf + g];
                mma_f16(o[nf], pa[kc], b0, b1);
            }
        }

        __syncthreads();
        if (t + 2 < NT) { loadTile(t + 2, t & 1); CP_COMMIT(); }
    }

    // ---- diagonal term ----
    __syncthreads();
    #pragma unroll
    for (int i = 0; i < 8; i++) {
        int f4 = tid + i * 256;
        int row = f4 >> 4;
        int s = (f4 & 15) << 2;
        *(float4*)&Ks[row * FKS + s] =
            *(const float4*)(XQKp + base + (size_t)(q0 + row) * 512 + s);
        *(float4*)&Qs[row * FKS + s] =
            *(const float4*)(XQVp + base + (size_t)(q0 + row) * 512 + s);
    }
    __syncthreads();

    float sd0 = 0.f, sd1 = 0.f;
    #pragma unroll
    for (int t = 0; t < 8; t++) {
        sd0 += __uint_as_float(qa[t][0]) * Ks[r0 * FKS + 8 * t + cc];
        sd1 += __uint_as_float(qa[t][1]) * Ks[(r0 + 8) * FKS + 8 * t + cc];
        sd0 += __uint_as_float(qa[t][2]) * Ks[r0 * FKS + 8 * t + cc + 4];
        sd1 += __uint_as_float(qa[t][3]) * Ks[(r0 + 8) * FKS + 8 * t + cc + 4];
    }
    sd0 += __shfl_xor_sync(0xffffffffu, sd0, 1);
    sd0 += __shfl_xor_sync(0xffffffffu, sd0, 2);
    sd1 += __shfl_xor_sync(0xffffffffu, sd1, 1);
    sd1 += __shfl_xor_sync(0xffffffffu, sd1, 2);

    float mn0 = fmaxf(m0, sd0), mn1 = fmaxf(m1, sd1);
    float al0 = __expf(m0 - mn0), al1 = __expf(m1 - mn1);
    float pd0 = __expf(sd0 - mn0), pd1 = __expf(sd1 - mn1);
    float li0 = 1.f / (l0 * al0 + pd0);
    float li1 = 1.f / (l1 * al1 + pd1);

    #pragma unroll
    for (int nf = 0; nf < 8; nf++) {
        int col = 8 * nf + 2 * cc;
        float2 xv0 = *(float2*)&Qs[r0 * FKS + col];
        float2 xv1 = *(float2*)&Qs[(r0 + 8) * FKS + col];
        float2 out0, out1;
        out0.x = cvt_tf32((o[nf][0] * al0 + pd0 * xv0.x) * li0);
        out0.y = cvt_tf32((o[nf][1] * al0 + pd0 * xv0.y) * li0);
        out1.x = cvt_tf32((o[nf][2] * al1 + pd1 * xv1.x) * li1);
        out1.y = cvt_tf32((o[nf][3] * al1 + pd1 * xv1.y) * li1);
        *(float2*)(Op + base + (size_t)(q0 + r0) * 512 + col) = out0;
        *(float2*)(Op + base + (size_t)(q0 + r0 + 8) * 512 + col) = out1;
    }
}

// -------------------- launch -----------------------------------------------
extern "C" void kernel_launch(void* const* d_in, const int* in_sizes, int n_in,
                              void* d_out, int out_size)
{
    const float* xq = (const float*)d_in[0];
    const float* xk = (const float*)d_in[1];
    const float* xv = (const float*)d_in[2];
    const float* Wq = (const float*)d_in[3];
    const float* Wk = (const float*)d_in[4];
    const float* Wv = (const float*)d_in[5];
    const float* Wo = (const float*)d_in[6];
    const float* bo = (const float*)d_in[7];
    float* out = (float*)d_out;

    const int D = 512;
    const int Mrows = in_sizes[0] / D;      // 8192
    const int n = Mrows / 4;                 // 2048

    float *Qb, *Kb, *Vb, *XQKb, *XQVb, *AOb;
    float *XQc, *XKc, *XVc, *WqT, *WkT, *WvT, *WoT;
    uint32_t* Vhb;
    cudaGetSymbolAddress((void**)&Qb,   g_Q);
    cudaGetSymbolAddress((void**)&Kb,   g_K);
    cudaGetSymbolAddress((void**)&Vb,   g_V);
    cudaGetSymbolAddress((void**)&XQKb, g_XQK);
    cudaGetSymbolAddress((void**)&XQVb, g_XQV);
    cudaGetSymbolAddress((void**)&AOb,  g_AO);
    cudaGetSymbolAddress((void**)&XQc,  g_XQc);
    cudaGetSymbolAddress((void**)&XKc,  g_XKc);
    cudaGetSymbolAddress((void**)&XVc,  g_XVc);
    cudaGetSymbolAddress((void**)&WqT,  g_WqT);
    cudaGetSymbolAddress((void**)&WkT,  g_WkT);
    cudaGetSymbolAddress((void**)&WvT,  g_WvT);
    cudaGetSymbolAddress((void**)&WoT,  g_WoT);
    cudaGetSymbolAddress((void**)&Vhb,  g_Vh);

    const int cvtBlocks = (Mrows * D) / (256 * 4);
    cvt_tf32_copy<<<cvtBlocks, 256>>>(xq, XQc);
    cvt_tf32_copy<<<cvtBlocks, 256>>>(xk, XKc);
    cvt_tf32_copy<<<cvtBlocks, 256>>>(xv, XVc);
    dim3 tb(32, 8), tg(16, 16);
    transpose512_cvt<<<tg, tb>>>(Wq, WqT);
    transpose512_cvt<<<tg, tb>>>(Wk, WkT);
    transpose512_cvt<<<tg, tb>>>(Wv, WvT);
    transpose512_cvt<<<tg, tb>>>(Wo, WoT);

    cudaFuncSetAttribute(gemm_mma, cudaFuncAttributeMaxDynamicSharedMemorySize,
                         GM_SMEM);
    dim3 gg(D / 128, Mrows / 128);
    // Q, K rounded to tf32 in epilogue (consumed by tf32 attention mma)
    gemm_mma<<<gg, 256, GM_SMEM>>>(XQc, WqT, nullptr, Qb,   Mrows, D, D, 1);
    gemm_mma<<<gg, 256, GM_SMEM>>>(XKc, WkT, nullptr, Kb,   Mrows, D, D, 1);
    gemm_mma<<<gg, 256, GM_SMEM>>>(XVc, WvT, nullptr, Vb,   Mrows, D, D, 0);
    gemm_mma<<<gg, 256, GM_SMEM>>>(XQc, WkT, nullptr, XQKb, Mrows, D, D, 0);
    gemm_mma<<<gg, 256, GM_SMEM>>>(XQc, WvT, nullptr, XQVb, Mrows, D, D, 0);

    conv_v_half<<<(4 * 8 * 1024 * 64) / 256, 256>>>(Vb, Vhb, n);

    cudaFuncSetAttribute(flash_attn_mma,
                         cudaFuncAttributeMaxDynamicSharedMemorySize, FA_SMEM);
    flash_attn_mma<<<dim3(n / 128, 8, 4), 256, FA_SMEM>>>(Qb, Kb, Vhb, XQKb,
                                                          XQVb, AOb, n);

    gemm_mma<<<gg, 256, GM_SMEM>>>(AOb, WoT, bo, out, Mrows, D, D, 0);
}